// round 7
// baseline (speedup 1.0000x reference)
#include <cuda_runtime.h>
#include <cuda_bf16.h>
#include <cstdint>
#include <cstddef>

// ---------------- problem constants ----------------
#define T_DIM 2048
#define B_DIM 16
#define N_DIM 1024
#define ROWS  (T_DIM * B_DIM)          // 32768 rows of X (flattened [T,B])

// ---------------- device scratch (static, no dynamic allocs) ----------------
__device__ float g_Wmod[N_DIM * N_DIM];      // tf32-rounded (W + I)
__device__ float g_scores[ROWS];             // pre-softmax scores [T,B]
__device__ float g_attn[ROWS];               // softmax result [T,B]
__device__ float g_zpart[4][B_DIM * N_DIM];  // deterministic partial sums for z

// ---------------- helpers ----------------
__device__ __forceinline__ uint32_t smem_u32(const void* p) {
    uint32_t a;
    asm("{ .reg .u64 t; cvta.to.shared.u64 t, %1; cvt.u32.u64 %0, t; }" : "=r"(a) : "l"(p));
    return a;
}

// cvt.rna.tf32.f32 destination is a .b32 register -> must use "=r", not "=f"
__device__ __forceinline__ float to_tf32(float x) {
    uint32_t r;
    asm("cvt.rna.tf32.f32 %0, %1;" : "=r"(r) : "f"(x));
    return __uint_as_float(r);
}

__device__ __forceinline__ float tanh_fast(float x) {
    float ax = fabsf(x);
    float t  = __expf(-2.0f * ax);
    float r  = __fdividef(1.0f - t, 1.0f + t);
    return copysignf(r, x);
}

__device__ __forceinline__ void cp_async16(uint32_t dst_smem, const void* gsrc) {
    asm volatile("cp.async.cg.shared.global [%0], [%1], 16;\n"
                 :: "r"(dst_smem), "l"(__cvta_generic_to_global(gsrc)) : "memory");
}
#define CP_ASYNC_COMMIT() asm volatile("cp.async.commit_group;\n" ::: "memory")
#define CP_ASYNC_WAIT(n)  asm volatile("cp.async.wait_group %0;\n" :: "n"(n) : "memory")

// mma.sync m16n8k8 tf32 (sm_80 baseline PTX — legal for the compute_100 target)
__device__ __forceinline__ void mma_tf32(float& c0, float& c1, float& c2, float& c3,
                                         uint32_t a0, uint32_t a1, uint32_t a2, uint32_t a3,
                                         uint32_t b0, uint32_t b1) {
    asm volatile(
        "mma.sync.aligned.m16n8k8.row.col.f32.tf32.tf32.f32 "
        "{%0,%1,%2,%3}, {%4,%5,%6,%7}, {%8,%9}, {%0,%1,%2,%3};\n"
        : "+f"(c0), "+f"(c1), "+f"(c2), "+f"(c3)
        : "r"(a0), "r"(a1), "r"(a2), "r"(a3), "r"(b0), "r"(b1));
}

// ---------------- kernel A geometry ----------------
// CTA tile: M=128 rows x N=256 cols, K in chunks of 16, double-buffered.
// SMEM rows padded to 20 floats (80B): conflict-free fragment LDS, 16B-aligned rows.
static constexpr int KCH      = 16;
static constexpr int AS_STR   = 20;                    // floats per smem row
static constexpr int A_F      = 128 * AS_STR;          // 2560 floats
static constexpr int B_F      = 256 * AS_STR;          // 5120 floats
static constexpr int STAGE_F  = A_F + B_F;             // 7680 floats
static constexpr int SCORE_F  = 4 * 128;               // [wn][row]
static constexpr int SMEM_F   = 2 * STAGE_F + SCORE_F; // 15872 floats
static constexpr int SMEM_BYTES = SMEM_F * 4;          // 63488 B

// ---------------- kernel 0: W' = rna_tf32(W + I) ----------------
__global__ void prep_w_kernel(const float* __restrict__ Ww) {
    int i = blockIdx.x * blockDim.x + threadIdx.x;
    if (i < N_DIM * N_DIM) {
        float w = Ww[i];
        if ((i >> 10) == (i & (N_DIM - 1))) w += 1.0f;   // fold residual
        g_Wmod[i] = to_tf32(w);
    }
}

// ---------------- kernel A: fused tf32 GEMM + tanh + v-dot -> scores ----------------
__global__ void __launch_bounds__(256, 1)
fused_gemm_score_kernel(const float* __restrict__ X,
                        const float* __restrict__ Wb,
                        const float* __restrict__ Vw) {
    extern __shared__ float smem[];
    const int tid  = threadIdx.x;
    const int warp = tid >> 5, lane = tid & 31;
    const int wm = warp >> 2, wn = warp & 3;      // 2 x 4 warp grid
    const int g  = lane >> 2, t4 = lane & 3;      // quad layout
    const int row_base = blockIdx.x * 128;

    float* score_part = smem + 2 * STAGE_F;       // [4][128]

    float score_acc[8];
    #pragma unroll
    for (int i = 0; i < 8; ++i) score_acc[i] = 0.0f;

    for (int nc = 0; nc < 4; ++nc) {
        const float* Bsrc = g_Wmod + (size_t)(nc * 256) * N_DIM;

        float acc[4][8][4];
        #pragma unroll
        for (int mf = 0; mf < 4; ++mf)
            #pragma unroll
            for (int nf = 0; nf < 8; ++nf)
                #pragma unroll
                for (int c = 0; c < 4; ++c) acc[mf][nf][c] = 0.0f;

        // ---- stage loader: A via LDG+cvt+STS, B via cp.async (pre-rounded) ----
        auto load_stage = [&](int k0, int s) {
            float* As_ = smem + s * STAGE_F;
            float* Bs_ = As_ + A_F;
            #pragma unroll
            for (int i = 0; i < 2; ++i) {          // A: 512 float4s / 256 thr
                const int fid = tid + i * 256;
                const int r = fid >> 2, c = (fid & 3) * 4;
                float4 v = *(const float4*)(X + (size_t)(row_base + r) * N_DIM + k0 + c);
                v.x = to_tf32(v.x); v.y = to_tf32(v.y);
                v.z = to_tf32(v.z); v.w = to_tf32(v.w);
                *(float4*)(As_ + r * AS_STR + c) = v;
            }
            #pragma unroll
            for (int i = 0; i < 4; ++i) {          // B: 1024 float4s / 256 thr
                const int fid = tid + i * 256;
                const int r = fid >> 2, c = (fid & 3) * 4;
                cp_async16(smem_u32(Bs_ + r * AS_STR + c),
                           Bsrc + (size_t)r * N_DIM + k0 + c);
            }
            CP_ASYNC_COMMIT();
        };

        load_stage(0, 0);

        for (int kk = 0; kk < N_DIM / KCH; ++kk) {
            const int cur = kk & 1;
            if (kk + 1 < N_DIM / KCH) {
                load_stage((kk + 1) * KCH, cur ^ 1);
                CP_ASYNC_WAIT(1);
            } else {
                CP_ASYNC_WAIT(0);
            }
            __syncthreads();

            const float* As_ = smem + cur * STAGE_F;
            const float* Bs_ = As_ + A_F;

            #pragma unroll
            for (int k8 = 0; k8 < 2; ++k8) {
                const int kb = k8 * 8;
                uint32_t a[4][4];
                #pragma unroll
                for (int mf = 0; mf < 4; ++mf) {
                    const int r0 = wm * 64 + mf * 16 + g;
                    a[mf][0] = __float_as_uint(As_[(r0    ) * AS_STR + kb + t4    ]);
                    a[mf][1] = __float_as_uint(As_[(r0 + 8) * AS_STR + kb + t4    ]);
                    a[mf][2] = __float_as_uint(As_[(r0    ) * AS_STR + kb + t4 + 4]);
                    a[mf][3] = __float_as_uint(As_[(r0 + 8) * AS_STR + kb + t4 + 4]);
                }
                uint32_t b[8][2];
                #pragma unroll
                for (int nf = 0; nf < 8; ++nf) {
                    const int n0 = wn * 64 + nf * 8 + g;
                    b[nf][0] = __float_as_uint(Bs_[n0 * AS_STR + kb + t4    ]);
                    b[nf][1] = __float_as_uint(Bs_[n0 * AS_STR + kb + t4 + 4]);
                }
                #pragma unroll
                for (int mf = 0; mf < 4; ++mf)
                    #pragma unroll
                    for (int nf = 0; nf < 8; ++nf)
                        mma_tf32(acc[mf][nf][0], acc[mf][nf][1],
                                 acc[mf][nf][2], acc[mf][nf][3],
                                 a[mf][0], a[mf][1], a[mf][2], a[mf][3],
                                 b[nf][0], b[nf][1]);
            }
            __syncthreads();
        }

        // ---- epilogue: tanh(af+b)*v, reduce over this chunk's 256 cols ----
        #pragma unroll
        for (int mf = 0; mf < 4; ++mf) {
            #pragma unroll
            for (int nf = 0; nf < 8; ++nf) {
                const int colg = nc * 256 + wn * 64 + nf * 8 + 2 * t4;
                const float wb0 = Wb[colg], wb1 = Wb[colg + 1];
                const float v0  = Vw[colg], v1  = Vw[colg + 1];
                score_acc[mf * 2 + 0] += tanh_fast(acc[mf][nf][0] + wb0) * v0
                                       + tanh_fast(acc[mf][nf][1] + wb1) * v1;
                score_acc[mf * 2 + 1] += tanh_fast(acc[mf][nf][2] + wb0) * v0
                                       + tanh_fast(acc[mf][nf][3] + wb1) * v1;
            }
        }
    }

    // quad reduce (lanes sharing a row differ only in t4)
    #pragma unroll
    for (int i = 0; i < 8; ++i) {
        float s = score_acc[i];
        s += __shfl_xor_sync(0xffffffffu, s, 1);
        s += __shfl_xor_sync(0xffffffffu, s, 2);
        score_acc[i] = s;
    }
    if (t4 == 0) {
        #pragma unroll
        for (int i = 0; i < 8; ++i) {
            const int r = wm * 64 + (i >> 1) * 16 + g + (i & 1) * 8;
            score_part[wn * 128 + r] = score_acc[i];
        }
    }
    __syncthreads();
    if (tid < 128) {
        g_scores[row_base + tid] = score_part[tid] + score_part[128 + tid]
                                 + score_part[256 + tid] + score_part[384 + tid];
    }
}

// ---------------- kernel B: softmax over T per batch column ----------------
__global__ void softmax_kernel(const unsigned char* __restrict__ mask) {
    const int b = blockIdx.x;
    const int tid = threadIdx.x;
    __shared__ float red[256];

    float s[8];
    float m = -1e30f;
    #pragma unroll
    for (int i = 0; i < 8; ++i) {
        const int t = tid + i * 256;
        const bool pad = mask[(size_t)t * B_DIM + b] != 0;
        s[i] = pad ? -1e30f : g_scores[(size_t)t * B_DIM + b];
        m = fmaxf(m, s[i]);
    }
    red[tid] = m;
    __syncthreads();
    for (int o = 128; o > 0; o >>= 1) {
        if (tid < o) red[tid] = fmaxf(red[tid], red[tid + o]);
        __syncthreads();
    }
    const float gm = red[0];
    __syncthreads();

    float e[8];
    float lsum = 0.0f;
    #pragma unroll
    for (int i = 0; i < 8; ++i) {
        e[i] = __expf(s[i] - gm);
        lsum += e[i];
    }
    red[tid] = lsum;
    __syncthreads();
    for (int o = 128; o > 0; o >>= 1) {
        if (tid < o) red[tid] += red[tid + o];
        __syncthreads();
    }
    const float inv = __fdividef(1.0f, red[0]);

    #pragma unroll
    for (int i = 0; i < 8; ++i) {
        const int t = tid + i * 256;
        g_attn[(size_t)t * B_DIM + b] = e[i] * inv;
    }
}

// ---------------- kernel C: z partials (deterministic 4-way T split) ----------------
__global__ void __launch_bounds__(256)
z_partial_kernel(const float* __restrict__ X) {
    __shared__ float a_sh[512];
    const int b  = blockIdx.x;       // 0..15
    const int nt = blockIdx.y;       // 0..3  (256-col tile)
    const int tc = blockIdx.z;       // 0..3  (512-t chunk)
    const int tid = threadIdx.x;

    for (int i = tid; i < 512; i += 256)
        a_sh[i] = g_attn[(size_t)(tc * 512 + i) * B_DIM + b];
    __syncthreads();

    const int col = nt * 256 + tid;
    const float* xp = X + ((size_t)(tc * 512) * B_DIM + b) * N_DIM + col;
    float acc = 0.0f;
    #pragma unroll 8
    for (int t = 0; t < 512; ++t)
        acc = fmaf(a_sh[t], xp[(size_t)t * B_DIM * N_DIM], acc);

    g_zpart[tc][b * N_DIM + col] = acc;
}

// ---------------- kernel D: finalize -> d_out = [z (16384) | attn (32768)] ----------------
__global__ void finalize_kernel(float* __restrict__ out, int total) {
    const int i = blockIdx.x * blockDim.x + threadIdx.x;
    if (i >= total) return;

    if (total >= B_DIM * N_DIM + ROWS) {
        if (i < B_DIM * N_DIM)
            out[i] = g_zpart[0][i] + g_zpart[1][i] + g_zpart[2][i] + g_zpart[3][i];
        else if (i < B_DIM * N_DIM + ROWS)
            out[i] = g_attn[i - B_DIM * N_DIM];
        else
            out[i] = 0.0f;
    } else if (total == ROWS) {
        out[i] = g_attn[i];
    } else if (i < B_DIM * N_DIM) {
        out[i] = g_zpart[0][i] + g_zpart[1][i] + g_zpart[2][i] + g_zpart[3][i];
    }
}

// ---------------- launch ----------------
extern "C" void kernel_launch(void* const* d_in, const int* in_sizes, int n_in,
                              void* d_out, int out_size) {
    const float*         X    = (const float*)d_in[0];          // [T,B,N]
    const unsigned char* mask = (const unsigned char*)d_in[1];  // [T,B] bool
    const float*         Ww   = (const float*)d_in[2];          // [N,N]
    const float*         Wb   = (const float*)d_in[3];          // [N]
    const float*         Vw   = (const float*)d_in[4];          // [1,N]
    float*               out  = (float*)d_out;

    cudaFuncSetAttribute(fused_gemm_score_kernel,
                         cudaFuncAttributeMaxDynamicSharedMemorySize, SMEM_BYTES);

    prep_w_kernel<<<(N_DIM * N_DIM + 255) / 256, 256>>>(Ww);
    fused_gemm_score_kernel<<<ROWS / 128, 256, SMEM_BYTES>>>(X, Wb, Vw);
    softmax_kernel<<<B_DIM, 256>>>(mask);
    dim3 zgrid(B_DIM, 4, 4);
    z_partial_kernel<<<zgrid, 256>>>(X);
    finalize_kernel<<<(out_size + 255) / 256, 256>>>(out, out_size);
}

// round 8
// speedup vs baseline: 1.5651x; 1.5651x over previous
#include <cuda_runtime.h>
#include <cuda_bf16.h>
#include <cstdint>
#include <cstddef>

// ---------------- problem constants ----------------
#define T_DIM 2048
#define B_DIM 16
#define N_DIM 1024
#define ROWS  (T_DIM * B_DIM)          // 32768 rows of X (flattened [T,B])

// ---------------- device scratch (static, no dynamic allocs) ----------------
// W' = tf32(W + I) stored in MMA-fragment-major order:
// [nc:4][kk:32][k8:4][wn:4][j:4][lane:32][e:4]  (1M floats = 4 MB)
__device__ float g_Wfrag[N_DIM * N_DIM];
__device__ float g_scores[ROWS];              // pre-softmax scores [T,B]
__device__ float g_attn[ROWS];                // softmax result [T,B]
__device__ float g_zpart[64][B_DIM * N_DIM];  // deterministic partial sums for z (4 MB)

// ---------------- helpers ----------------
__device__ __forceinline__ uint32_t smem_u32(const void* p) {
    uint32_t a;
    asm("{ .reg .u64 t; cvta.to.shared.u64 t, %1; cvt.u32.u64 %0, t; }" : "=r"(a) : "l"(p));
    return a;
}

// cvt.rna.tf32.f32: destination is a .b32 register
__device__ __forceinline__ float to_tf32(float x) {
    uint32_t r;
    asm("cvt.rna.tf32.f32 %0, %1;" : "=r"(r) : "f"(x));
    return __uint_as_float(r);
}

__device__ __forceinline__ float tanh_fast(float x) {
    float ax = fabsf(x);
    float t  = __expf(-2.0f * ax);
    float r  = __fdividef(1.0f - t, 1.0f + t);
    return copysignf(r, x);
}

__device__ __forceinline__ void cp_async16(uint32_t dst_smem, const void* gsrc) {
    asm volatile("cp.async.cg.shared.global [%0], [%1], 16;\n"
                 :: "r"(dst_smem), "l"(__cvta_generic_to_global(gsrc)) : "memory");
}
#define CP_ASYNC_COMMIT() asm volatile("cp.async.commit_group;\n" ::: "memory")
#define CP_ASYNC_WAIT(n)  asm volatile("cp.async.wait_group %0;\n" :: "n"(n) : "memory")

// mma.sync m16n8k8 tf32 (sm_80 baseline PTX)
__device__ __forceinline__ void mma_tf32(float& c0, float& c1, float& c2, float& c3,
                                         uint32_t a0, uint32_t a1, uint32_t a2, uint32_t a3,
                                         uint32_t b0, uint32_t b1) {
    asm volatile(
        "mma.sync.aligned.m16n8k8.row.col.f32.tf32.tf32.f32 "
        "{%0,%1,%2,%3}, {%4,%5,%6,%7}, {%8,%9}, {%0,%1,%2,%3};\n"
        : "+f"(c0), "+f"(c1), "+f"(c2), "+f"(c3)
        : "r"(a0), "r"(a1), "r"(a2), "r"(a3), "r"(b0), "r"(b1));
}

// ---------------- kernel A geometry ----------------
// CTA tile: M=128 x N=256 per nc pass (4 passes), K chunks of 32, 4-stage cp.async ring.
static constexpr int KCH        = 32;
static constexpr int NCHUNKS    = N_DIM / KCH;          // 32 k-chunks per nc pass
static constexpr int A_STR      = 36;                   // A smem row stride (floats): conflict-free
static constexpr int A_STAGE_F  = 128 * A_STR;          // 4608 floats (18432 B)
static constexpr int B_STAGE_F  = 4 * 4 * 4 * 32 * 4;   // [k8][wn][j][lane][e] = 8192 floats (32768 B)
static constexpr int STAGE_F    = A_STAGE_F + B_STAGE_F;  // 12800 floats (51200 B)
static constexpr int NSTAGE     = 4;
static constexpr int SCORE_F    = 4 * 128;
static constexpr int SMEM_F     = NSTAGE * STAGE_F + SCORE_F;   // 51712 floats
static constexpr int SMEM_BYTES = SMEM_F * 4;                   // 206848 B

// ---------------- kernel 0: W' -> fragment-major tf32 ----------------
__global__ void prep_wfrag_kernel(const float* __restrict__ Ww) {
    const int i = blockIdx.x * blockDim.x + threadIdx.x;
    if (i >= N_DIM * N_DIM) return;
    const int e    = i & 3;
    const int lane = (i >> 2) & 31;
    const int j    = (i >> 7) & 3;
    const int wn   = (i >> 9) & 3;
    const int k8   = (i >> 11) & 3;
    const int kk   = (i >> 13) & 31;
    const int nc   = (i >> 18) & 3;
    const int n = nc * 256 + wn * 64 + (j * 2 + (e >> 1)) * 8 + (lane >> 2);
    const int k = kk * KCH + k8 * 8 + (lane & 3) + (e & 1) * 4;
    float w = Ww[n * N_DIM + k];
    if (n == k) w += 1.0f;                 // fold residual: af = X (W+I)^T + b
    g_Wfrag[i] = to_tf32(w);
}

// ---------------- kernel A: fused tf32 GEMM + tanh + v-dot -> scores ----------------
__global__ void __launch_bounds__(256, 1)
fused_gemm_score_kernel(const float* __restrict__ X,
                        const float* __restrict__ Wb,
                        const float* __restrict__ Vw) {
    extern __shared__ float smem[];
    const int tid  = threadIdx.x;
    const int warp = tid >> 5, lane = tid & 31;
    const int wm = warp >> 2, wn = warp & 3;      // 2 x 4 warp grid
    const int g  = lane >> 2, t4 = lane & 3;      // quad layout
    const int row_base = blockIdx.x * 128;

    float* score_part = smem + NSTAGE * STAGE_F;  // [4][128]

    float score_acc[8];
    #pragma unroll
    for (int i = 0; i < 8; ++i) score_acc[i] = 0.0f;

    for (int nc = 0; nc < 4; ++nc) {
        float acc[4][8][4];
        #pragma unroll
        for (int mf = 0; mf < 4; ++mf)
            #pragma unroll
            for (int nf = 0; nf < 8; ++nf)
                #pragma unroll
                for (int c = 0; c < 4; ++c) acc[mf][nf][c] = 0.0f;

        // ---- stage loader: all cp.async (A relies on HW tf32 truncation) ----
        auto load_stage = [&](int kk, int s) {
            float* As_ = smem + s * STAGE_F;
            float* Bs_ = As_ + A_STAGE_F;
            #pragma unroll
            for (int i = 0; i < 4; ++i) {          // A: 1024 float4 / 256 thr
                const int fid = tid + i * 256;
                const int r = fid >> 3, c8 = fid & 7;
                cp_async16(smem_u32(As_ + r * A_STR + c8 * 4),
                           X + (size_t)(row_base + r) * N_DIM + kk * KCH + c8 * 4);
            }
            const float* Wsrc = g_Wfrag + (size_t)(nc * NCHUNKS + kk) * B_STAGE_F;
            #pragma unroll
            for (int i = 0; i < 8; ++i) {          // B: 2048 float4 / 256 thr, linear
                const int fid = tid + i * 256;
                cp_async16(smem_u32(Bs_ + fid * 4), Wsrc + fid * 4);
            }
        };

        // prologue: fill 3 stages
        #pragma unroll
        for (int p = 0; p < 3; ++p) { load_stage(p, p); CP_ASYNC_COMMIT(); }

        for (int kk = 0; kk < NCHUNKS; ++kk) {
            CP_ASYNC_WAIT(2);
            __syncthreads();
            // issue next stage into buffer freed at kk-1 (safe: sync above)
            if (kk + 3 < NCHUNKS) load_stage(kk + 3, (kk + 3) & 3);
            CP_ASYNC_COMMIT();                    // always commit (empty ok) -> uniform bookkeeping

            const float* As_ = smem + (kk & 3) * STAGE_F;
            const float* Bs_ = As_ + A_STAGE_F;

            #pragma unroll
            for (int k8 = 0; k8 < 4; ++k8) {
                const int kb = k8 * 8;
                uint32_t a[4][4];
                #pragma unroll
                for (int mf = 0; mf < 4; ++mf) {
                    const int r0 = wm * 64 + mf * 16 + g;
                    a[mf][0] = __float_as_uint(As_[(r0    ) * A_STR + kb + t4    ]);
                    a[mf][1] = __float_as_uint(As_[(r0 + 8) * A_STR + kb + t4    ]);
                    a[mf][2] = __float_as_uint(As_[(r0    ) * A_STR + kb + t4 + 4]);
                    a[mf][3] = __float_as_uint(As_[(r0 + 8) * A_STR + kb + t4 + 4]);
                }
                // B fragments: 4 conflict-free LDS.128 per warp
                float4 bf[4];
                const float4* Bq = (const float4*)Bs_ + (size_t)(k8 * 4 + wn) * 128;
                #pragma unroll
                for (int j = 0; j < 4; ++j) bf[j] = Bq[j * 32 + lane];

                #pragma unroll
                for (int mf = 0; mf < 4; ++mf) {
                    #pragma unroll
                    for (int j = 0; j < 4; ++j) {
                        mma_tf32(acc[mf][2*j  ][0], acc[mf][2*j  ][1],
                                 acc[mf][2*j  ][2], acc[mf][2*j  ][3],
                                 a[mf][0], a[mf][1], a[mf][2], a[mf][3],
                                 __float_as_uint(bf[j].x), __float_as_uint(bf[j].y));
                        mma_tf32(acc[mf][2*j+1][0], acc[mf][2*j+1][1],
                                 acc[mf][2*j+1][2], acc[mf][2*j+1][3],
                                 a[mf][0], a[mf][1], a[mf][2], a[mf][3],
                                 __float_as_uint(bf[j].z), __float_as_uint(bf[j].w));
                    }
                }
            }
        }

        // ---- epilogue: tanh(af+b)*v, reduce over this pass's 256 cols (regs only) ----
        #pragma unroll
        for (int mf = 0; mf < 4; ++mf) {
            #pragma unroll
            for (int nf = 0; nf < 8; ++nf) {
                const int colg = nc * 256 + wn * 64 + nf * 8 + 2 * t4;
                const float wb0 = Wb[colg], wb1 = Wb[colg + 1];
                const float v0  = Vw[colg], v1  = Vw[colg + 1];
                score_acc[mf * 2 + 0] += tanh_fast(acc[mf][nf][0] + wb0) * v0
                                       + tanh_fast(acc[mf][nf][1] + wb1) * v1;
                score_acc[mf * 2 + 1] += tanh_fast(acc[mf][nf][2] + wb0) * v0
                                       + tanh_fast(acc[mf][nf][3] + wb1) * v1;
            }
        }
    }

    // quad reduce (lanes sharing a row differ only in t4)
    #pragma unroll
    for (int i = 0; i < 8; ++i) {
        float s = score_acc[i];
        s += __shfl_xor_sync(0xffffffffu, s, 1);
        s += __shfl_xor_sync(0xffffffffu, s, 2);
        score_acc[i] = s;
    }
    __syncthreads();                              // all compute done before score_part writes
    if (t4 == 0) {
        #pragma unroll
        for (int i = 0; i < 8; ++i) {
            const int r = wm * 64 + (i >> 1) * 16 + g + (i & 1) * 8;
            score_part[wn * 128 + r] = score_acc[i];
        }
    }
    __syncthreads();
    if (tid < 128) {
        g_scores[row_base + tid] = score_part[tid] + score_part[128 + tid]
                                 + score_part[256 + tid] + score_part[384 + tid];
    }
}

// ---------------- kernel B: softmax over T per batch column ----------------
__global__ void softmax_kernel(const unsigned char* __restrict__ mask) {
    const int b = blockIdx.x;
    const int tid = threadIdx.x;
    __shared__ float red[256];

    float s[8];
    float m = -1e30f;
    #pragma unroll
    for (int i = 0; i < 8; ++i) {
        const int t = tid + i * 256;
        const bool pad = mask[(size_t)t * B_DIM + b] != 0;
        s[i] = pad ? -1e30f : g_scores[(size_t)t * B_DIM + b];
        m = fmaxf(m, s[i]);
    }
    red[tid] = m;
    __syncthreads();
    for (int o = 128; o > 0; o >>= 1) {
        if (tid < o) red[tid] = fmaxf(red[tid], red[tid + o]);
        __syncthreads();
    }
    const float gm = red[0];
    __syncthreads();

    float e[8];
    float lsum = 0.0f;
    #pragma unroll
    for (int i = 0; i < 8; ++i) {
        e[i] = __expf(s[i] - gm);
        lsum += e[i];
    }
    red[tid] = lsum;
    __syncthreads();
    for (int o = 128; o > 0; o >>= 1) {
        if (tid < o) red[tid] += red[tid + o];
        __syncthreads();
    }
    const float inv = __fdividef(1.0f, red[0]);

    #pragma unroll
    for (int i = 0; i < 8; ++i) {
        const int t = tid + i * 256;
        g_attn[(size_t)t * B_DIM + b] = e[i] * inv;
    }
}

// ---------------- kernel C: z partials (64-way deterministic T split, float4) ----------------
__global__ void __launch_bounds__(256)
z_partial_kernel(const float* __restrict__ X) {
    __shared__ float a_sh[32];
    const int b  = blockIdx.x;       // 0..15
    const int tc = blockIdx.y;       // 0..63 (32-t chunk)
    const int tid = threadIdx.x;     // 256 thr -> 1024 cols as float4

    if (tid < 32) a_sh[tid] = g_attn[(size_t)(tc * 32 + tid) * B_DIM + b];
    __syncthreads();

    const float4* xp = (const float4*)X + ((size_t)(tc * 32) * B_DIM + b) * (N_DIM / 4) + tid;
    float4 acc = make_float4(0.f, 0.f, 0.f, 0.f);
    #pragma unroll
    for (int t = 0; t < 32; ++t) {
        const float4 v = xp[(size_t)t * B_DIM * (N_DIM / 4)];
        const float a = a_sh[t];
        acc.x = fmaf(a, v.x, acc.x);
        acc.y = fmaf(a, v.y, acc.y);
        acc.z = fmaf(a, v.z, acc.z);
        acc.w = fmaf(a, v.w, acc.w);
    }
    ((float4*)&g_zpart[tc][b * N_DIM])[tid] = acc;
}

// ---------------- kernel D: finalize -> d_out = [z (16384) | attn (32768)] ----------------
__global__ void finalize_kernel(float* __restrict__ out, int total) {
    const int i = blockIdx.x * blockDim.x + threadIdx.x;
    if (i >= total) return;

    if (total >= B_DIM * N_DIM + ROWS) {
        if (i < B_DIM * N_DIM) {
            float s = 0.0f;
            #pragma unroll 8
            for (int p = 0; p < 64; ++p) s += g_zpart[p][i];
            out[i] = s;
        } else if (i < B_DIM * N_DIM + ROWS) {
            out[i] = g_attn[i - B_DIM * N_DIM];
        } else {
            out[i] = 0.0f;
        }
    } else if (total == ROWS) {
        out[i] = g_attn[i];
    } else if (i < B_DIM * N_DIM) {
        float s = 0.0f;
        #pragma unroll 8
        for (int p = 0; p < 64; ++p) s += g_zpart[p][i];
        out[i] = s;
    }
}

// ---------------- launch ----------------
extern "C" void kernel_launch(void* const* d_in, const int* in_sizes, int n_in,
                              void* d_out, int out_size) {
    const float*         X    = (const float*)d_in[0];          // [T,B,N]
    const unsigned char* mask = (const unsigned char*)d_in[1];  // [T,B] bool
    const float*         Ww   = (const float*)d_in[2];          // [N,N]
    const float*         Wb   = (const float*)d_in[3];          // [N]
    const float*         Vw   = (const float*)d_in[4];          // [1,N]
    float*               out  = (float*)d_out;

    cudaFuncSetAttribute(fused_gemm_score_kernel,
                         cudaFuncAttributeMaxDynamicSharedMemorySize, SMEM_BYTES);

    prep_wfrag_kernel<<<(N_DIM * N_DIM + 255) / 256, 256>>>(Ww);
    fused_gemm_score_kernel<<<ROWS / 128, 256, SMEM_BYTES>>>(X, Wb, Vw);
    softmax_kernel<<<B_DIM, 256>>>(mask);
    dim3 zgrid(B_DIM, 64, 1);
    z_partial_kernel<<<zgrid, 256>>>(X);
    finalize_kernel<<<(out_size + 255) / 256, 256>>>(out, out_size);
}